// round 3
// baseline (speedup 1.0000x reference)
#include <cuda_runtime.h>
#include <math.h>

#define BB 2
#define NN 16000
#define EE 160000
#define KK 128
#define CC 64
#define LL 3
#define AW 448      // activation row: cos(128) | sin(128) | G(128) | H(64)
#define GOFF 256
#define HOFF 384

// ---------------- device scratch (no cudaMalloc allowed) ----------------
__device__ __align__(16) float d_ACT[BB * NN * AW];          // 57.3 MB
__device__ float d_smodes[KK * 2];
__device__ __align__(16) float d_Wct[LL * KK * CC * CC];     // 12.6 MB
__device__ __align__(16) float d_Wst[LL * KK * CC * CC];     // 12.6 MB
__device__ float d_A[BB * CC * 257];                         // A_c | A_s | a0
__device__ float d_FC[BB * KK * CC];
__device__ float d_FS[BB * KK * CC];
__device__ float d_F0[BB * CC];
__device__ __align__(16) float d_Wbig[BB * AW * CC];
__device__ __align__(16) float d_bias[BB * CC];
__device__ int   d_rowptr[BB * (NN + 1)];
__device__ int   d_cursor[BB * NN];
__device__ int   d_csrc[BB * EE];
__device__ float d_cw0[BB * EE];
__device__ float d_cw1[BB * EE];

__device__ __forceinline__ float gelu_t(float x) {
    // JAX default gelu (approximate=True, tanh form)
    float t = tanhf(0.7978845608028654f * (x + 0.044715f * x * x * x));
    return 0.5f * x * (1.0f + t);
}

// ---------------- setup kernels ----------------
__global__ void k_smodes(const float* __restrict__ modes, const float* __restrict__ lat) {
    int k = threadIdx.x;
    float inv0 = 0.5f + 1.5f * (1.0f / (1.0f + expf(-lat[0])));
    float inv1 = 0.5f + 1.5f * (1.0f / (1.0f + expf(-lat[1])));
    d_smodes[k * 2 + 0] = modes[k * 2 + 0] * inv0;
    d_smodes[k * 2 + 1] = modes[k * 2 + 1] * inv1;
}

__global__ void k_wt(const float* __restrict__ wc, const float* __restrict__ ws) {
    int tot = LL * KK * CC * CC;
    for (int i = blockIdx.x * blockDim.x + threadIdx.x; i < tot; i += gridDim.x * blockDim.x) {
        int o = i & 63; int t = i >> 6;
        int ii = t & 63; t >>= 6;
        int k = t & 127; int l = t >> 7;
        int srci = (((l * CC + ii) * CC + o) * KK) + k;
        d_Wct[i] = wc[srci];
        d_Wst[i] = ws[srci];
    }
}

__global__ void k_bases(const float* __restrict__ nodes) {
    int x = blockIdx.x, b = blockIdx.y, k = threadIdx.x;
    float n0 = nodes[(b * NN + x) * 2 + 0];
    float n1 = nodes[(b * NN + x) * 2 + 1];
    float t = n0 * d_smodes[k * 2 + 0] + n1 * d_smodes[k * 2 + 1];
    float s, c;
    sincosf(t, &s, &c);
    float* row = d_ACT + (size_t)(b * NN + x) * AW;
    row[k] = c;
    row[KK + k] = s;
}

__global__ void k_fc0(const float* __restrict__ xin, const float* __restrict__ W,
                      const float* __restrict__ bvec) {
    int tot = BB * NN * CC;
    for (int i = blockIdx.x * blockDim.x + threadIdx.x; i < tot; i += gridDim.x * blockDim.x) {
        int o = i & 63;
        int xn = i >> 6;
        const float* xr = xin + (size_t)xn * 3;
        d_ACT[(size_t)xn * AW + HOFF + o] =
            bvec[o] + W[o * 3] * xr[0] + W[o * 3 + 1] * xr[1] + W[o * 3 + 2] * xr[2];
    }
}

// ---------------- CSR build (once per launch) ----------------
__global__ void k_zero_cnt() {
    for (int i = blockIdx.x * blockDim.x + threadIdx.x; i < BB * NN; i += gridDim.x * blockDim.x)
        d_cursor[i] = 0;
}

__global__ void k_hist(const int* __restrict__ edges) {
    int tot = BB * EE;
    for (int i = blockIdx.x * blockDim.x + threadIdx.x; i < tot; i += gridDim.x * blockDim.x) {
        int b = i / EE;
        int tgt = edges[(size_t)i * 2];
        atomicAdd(&d_cursor[b * NN + tgt], 1);
    }
}

__global__ void k_scan() {
    int b = blockIdx.x, t = threadIdx.x;
    __shared__ int sm[1024];
    int base = t * 16;
    int loc[16];
    int run = 0;
#pragma unroll
    for (int j = 0; j < 16; ++j) {
        int idx = base + j;
        int c = (idx < NN) ? d_cursor[b * NN + idx] : 0;
        loc[j] = run;
        run += c;
    }
    sm[t] = run;
    __syncthreads();
    for (int off = 1; off < 1024; off <<= 1) {
        int v = (t >= off) ? sm[t - off] : 0;
        __syncthreads();
        sm[t] += v;
        __syncthreads();
    }
    int excl = sm[t] - run;
#pragma unroll
    for (int j = 0; j < 16; ++j) {
        int idx = base + j;
        if (idx < NN) {
            int p = excl + loc[j];
            d_rowptr[b * (NN + 1) + idx] = p;
            d_cursor[b * NN + idx] = p;
        }
    }
    if (t == 1023) d_rowptr[b * (NN + 1) + NN] = sm[1023];
}

__global__ void k_scatter(const int* __restrict__ edges, const float* __restrict__ egw) {
    int tot = BB * EE;
    for (int i = blockIdx.x * blockDim.x + threadIdx.x; i < tot; i += gridDim.x * blockDim.x) {
        int b = i / EE;
        int tgt = edges[(size_t)i * 2];
        int src = edges[(size_t)i * 2 + 1];
        int p = atomicAdd(&d_cursor[b * NN + tgt], 1);
        d_csrc[b * EE + p] = src;
        d_cw0[b * EE + p] = egw[(size_t)i * 2];
        d_cw1[b * EE + p] = egw[(size_t)i * 2 + 1];
    }
}

// ---------------- per-layer kernels ----------------
__global__ void k_zeroA() {
    for (int i = blockIdx.x * blockDim.x + threadIdx.x; i < BB * CC * 257; i += gridDim.x * blockDim.x)
        d_A[i] = 0.0f;
}

__global__ void k_a0(const float* __restrict__ nw) {
    int b = blockIdx.y, x0 = blockIdx.x * 320;
    int tid = threadIdx.x;
    int i = tid & 63, r = tid >> 6;
    float acc = 0.0f;
    for (int x = x0 + r; x < x0 + 320; x += 4)
        acc += d_ACT[(size_t)(b * NN + x) * AW + HOFF + i] * nw[b * NN + x];
    __shared__ float s[256];
    s[tid] = acc;
    __syncthreads();
    if (tid < 64)
        atomicAdd(&d_A[(b * CC + tid) * 257 + 256], s[tid] + s[tid + 64] + s[tid + 128] + s[tid + 192]);
}

// A[i][k] += sum_x Hw[x][i] * basis[x][k]  (split-K GEMM, 64x64 tiles, atomics reduce)
__global__ void k_spectral(const float* __restrict__ nw) {
    const int b = blockIdx.z, kt = blockIdx.y, ch = blockIdx.x;
    const int tid = threadIdx.x;
    __shared__ float sH[16][68];
    __shared__ float sB[16][68];
    float acc[4][4] = {};
    const int ty = tid >> 4, tx = tid & 15;
    const int nodeL = tid >> 4, seg = tid & 15;
    const int x0 = ch * 320, kbase = kt * 64;
    for (int s = 0; s < 20; ++s) {
        __syncthreads();
        int x = x0 + s * 16 + nodeL;
        const float* row = d_ACT + (size_t)(b * NN + x) * AW;
        float w = nw[b * NN + x];
        float4 hv = *(const float4*)(row + HOFF + seg * 4);
        float4 bv = *(const float4*)(row + kbase + seg * 4);
        sH[nodeL][seg * 4 + 0] = hv.x * w;
        sH[nodeL][seg * 4 + 1] = hv.y * w;
        sH[nodeL][seg * 4 + 2] = hv.z * w;
        sH[nodeL][seg * 4 + 3] = hv.w * w;
        sB[nodeL][seg * 4 + 0] = bv.x;
        sB[nodeL][seg * 4 + 1] = bv.y;
        sB[nodeL][seg * 4 + 2] = bv.z;
        sB[nodeL][seg * 4 + 3] = bv.w;
        __syncthreads();
#pragma unroll
        for (int jj = 0; jj < 16; ++jj) {
            float4 a = *(const float4*)&sH[jj][ty * 4];
            float4 bb = *(const float4*)&sB[jj][tx * 4];
            acc[0][0] += a.x * bb.x; acc[0][1] += a.x * bb.y; acc[0][2] += a.x * bb.z; acc[0][3] += a.x * bb.w;
            acc[1][0] += a.y * bb.x; acc[1][1] += a.y * bb.y; acc[1][2] += a.y * bb.z; acc[1][3] += a.y * bb.w;
            acc[2][0] += a.z * bb.x; acc[2][1] += a.z * bb.y; acc[2][2] += a.z * bb.z; acc[2][3] += a.z * bb.w;
            acc[3][0] += a.w * bb.x; acc[3][1] += a.w * bb.y; acc[3][2] += a.w * bb.z; acc[3][3] += a.w * bb.w;
        }
    }
#pragma unroll
    for (int u = 0; u < 4; ++u)
#pragma unroll
        for (int v = 0; v < 4; ++v)
            atomicAdd(&d_A[(b * CC + ty * 4 + u) * 257 + kbase + tx * 4 + v], acc[u][v]);
}

// G[t, c*2+d] = sum_{e:tgt=t} egw[e,d]*(H[src,c]-H[t,c]);  one warp per node
__global__ void k_grad() {
    int w = blockIdx.x * 8 + (threadIdx.x >> 5);
    int lane = threadIdx.x & 31;
    int b = w / NN, t = w % NN;
    const float* rowt = d_ACT + (size_t)(b * NN + t) * AW;
    float ht0 = rowt[HOFF + lane], ht1 = rowt[HOFF + 32 + lane];
    int rs = d_rowptr[b * (NN + 1) + t];
    int re = d_rowptr[b * (NN + 1) + t + 1];
    float a00 = 0.f, a01 = 0.f, a10 = 0.f, a11 = 0.f;
    for (int j = rs; j < re; ++j) {
        int s = d_csrc[b * EE + j];
        float w0 = d_cw0[b * EE + j];
        float w1 = d_cw1[b * EE + j];
        const float* rows = d_ACT + (size_t)(b * NN + s) * AW;
        float dd0 = rows[HOFF + lane] - ht0;
        float dd1 = rows[HOFF + 32 + lane] - ht1;
        a00 += w0 * dd0; a01 += w1 * dd0;
        a10 += w0 * dd1; a11 += w1 * dd1;
    }
    float* g = d_ACT + (size_t)(b * NN + t) * AW + GOFF;
    *(float2*)(g + 2 * lane) = make_float2(a00, a01);
    *(float2*)(g + 64 + 2 * lane) = make_float2(a10, a11);
}

// f_c = A_c Wc + A_s Ws ; f_s = A_c Ws - A_s Wc ; f_0 = a0 W0
__global__ void k_combine(int l, const float* __restrict__ w0in) {
    int k = blockIdx.x, b = blockIdx.y, o = threadIdx.x;
    __shared__ float sc[64], ss[64], s0[64];
    sc[o] = d_A[(b * CC + o) * 257 + k];
    ss[o] = d_A[(b * CC + o) * 257 + 128 + k];
    if (k == 0) s0[o] = d_A[(b * CC + o) * 257 + 256];
    __syncthreads();
    const float* wc = d_Wct + ((size_t)(l * KK + k) * CC) * CC + o;
    const float* ws = d_Wst + ((size_t)(l * KK + k) * CC) * CC + o;
    float fc = 0.f, fs = 0.f;
#pragma unroll 8
    for (int i = 0; i < 64; ++i) {
        float a = sc[i], s = ss[i];
        float Wc = wc[i * CC], Wsv = ws[i * CC];
        fc += a * Wc + s * Wsv;
        fs += a * Wsv - s * Wc;
    }
    d_FC[(b * KK + k) * CC + o] = fc;
    d_FS[(b * KK + k) * CC + o] = fs;
    if (k == 0) {
        float f0 = 0.f;
        for (int i = 0; i < 64; ++i) f0 += s0[i] * w0in[(l * CC + i) * CC + o];
        d_F0[b * CC + o] = f0;
    }
}

__global__ void k_wbig(int l, const float* __restrict__ gws, const float* __restrict__ wsw,
                       const float* __restrict__ wsb, const float* __restrict__ gwsb) {
    int idx = blockIdx.x * blockDim.x + threadIdx.x;
    int tot = BB * AW * CC;
    for (int i = idx; i < tot; i += gridDim.x * blockDim.x) {
        int bb = i / (AW * CC);
        int r = i % (AW * CC);
        int j = r / CC, o = r % CC;
        float v;
        if (j < 128)      v = 2.0f * d_FC[(bb * KK + j) * CC + o];
        else if (j < 256) v = -2.0f * d_FS[(bb * KK + (j - 128)) * CC + o];
        else if (j < 384) v = gws[(l * CC + o) * 128 + (j - 256)];
        else              v = wsw[(l * CC + o) * CC + (j - 384)];
        d_Wbig[i] = v;
    }
    if (idx < BB * CC) {
        int o = idx % CC;
        d_bias[idx] = d_F0[idx] + wsb[l * CC + o] + gwsb[l * CC + o];
    }
}

// h_new = ACT(N x 448) @ Wbig(448 x 64) + bias ; optional GELU ; write H slot
__global__ void k_gemm(int do_gelu) {
    const int b = blockIdx.z, nt = blockIdx.x;
    const int tid = threadIdx.x;
    __shared__ float As[2][16][68];
    __shared__ float Ws[2][16][64];
    const int ty = tid >> 4, tx = tid & 15;
    const int ln = tid >> 2, ls = tid & 3;
    const int wj = tid >> 4, wo = (tid & 15) * 4;
    const float* arow = d_ACT + (size_t)(b * NN + nt * 64 + ln) * AW;
    const float* Wb = d_Wbig + b * AW * CC;
    float acc[4][4] = {};

    float4 av = *(const float4*)(arow + ls * 4);
    float4 wv = *(const float4*)(Wb + wj * 64 + wo);
    As[0][ls * 4 + 0][ln] = av.x; As[0][ls * 4 + 1][ln] = av.y;
    As[0][ls * 4 + 2][ln] = av.z; As[0][ls * 4 + 3][ln] = av.w;
    *(float4*)&Ws[0][wj][wo] = wv;
    __syncthreads();
    int cur = 0;
    for (int s = 0; s < 28; ++s) {
        float4 av2, wv2;
        if (s < 27) {
            int nk = (s + 1) * 16;
            av2 = *(const float4*)(arow + nk + ls * 4);
            wv2 = *(const float4*)(Wb + (nk + wj) * 64 + wo);
        }
#pragma unroll
        for (int jj = 0; jj < 16; ++jj) {
            float4 a = *(const float4*)&As[cur][jj][ty * 4];
            float4 bb = *(const float4*)&Ws[cur][jj][tx * 4];
            acc[0][0] += a.x * bb.x; acc[0][1] += a.x * bb.y; acc[0][2] += a.x * bb.z; acc[0][3] += a.x * bb.w;
            acc[1][0] += a.y * bb.x; acc[1][1] += a.y * bb.y; acc[1][2] += a.y * bb.z; acc[1][3] += a.y * bb.w;
            acc[2][0] += a.z * bb.x; acc[2][1] += a.z * bb.y; acc[2][2] += a.z * bb.z; acc[2][3] += a.z * bb.w;
            acc[3][0] += a.w * bb.x; acc[3][1] += a.w * bb.y; acc[3][2] += a.w * bb.z; acc[3][3] += a.w * bb.w;
        }
        if (s < 27) {
            int nxt = cur ^ 1;
            As[nxt][ls * 4 + 0][ln] = av2.x; As[nxt][ls * 4 + 1][ln] = av2.y;
            As[nxt][ls * 4 + 2][ln] = av2.z; As[nxt][ls * 4 + 3][ln] = av2.w;
            *(float4*)&Ws[nxt][wj][wo] = wv2;
            __syncthreads();
            cur = nxt;
        }
    }
    float4 bias = *(const float4*)(d_bias + b * CC + tx * 4);
#pragma unroll
    for (int u = 0; u < 4; ++u) {
        float4 r;
        r.x = acc[u][0] + bias.x; r.y = acc[u][1] + bias.y;
        r.z = acc[u][2] + bias.z; r.w = acc[u][3] + bias.w;
        if (do_gelu) { r.x = gelu_t(r.x); r.y = gelu_t(r.y); r.z = gelu_t(r.z); r.w = gelu_t(r.w); }
        float* orow = d_ACT + (size_t)(b * NN + nt * 64 + ty * 4 + u) * AW + HOFF;
        *(float4*)(orow + tx * 4) = r;
    }
}

// out = fc2 @ gelu(fc1 @ h + b1) + b2, fused per node
__global__ void k_fc12(const float* __restrict__ W1, const float* __restrict__ b1,
                       const float* __restrict__ W2, const float* __restrict__ b2,
                       float* __restrict__ out) {
    __shared__ float sW1[128 * 65];
    __shared__ float sb1[128];
    __shared__ float sW2[128];
    __shared__ float sH[2][64];
    __shared__ float sred[8];
    int tid = threadIdx.x;
    for (int i = tid; i < 128 * 64; i += 256) {
        int o = i >> 6, c = i & 63;
        sW1[o * 65 + c] = W1[i];
    }
    if (tid < 128) { sb1[tid] = b1[tid]; sW2[tid] = W2[tid]; }
    int b = blockIdx.y;
    int nbase = blockIdx.x * 64;
    int half = tid >> 7, o = tid & 127;
    float b2v = b2[0];
    for (int m = 0; m < 32; ++m) {
        __syncthreads();
        if (tid < 128) {
            int hh = tid >> 6, c = tid & 63;
            sH[hh][c] = d_ACT[(size_t)(b * NN + nbase + m * 2 + hh) * AW + HOFF + c];
        }
        __syncthreads();
        float t = sb1[o];
#pragma unroll
        for (int c = 0; c < 64; ++c) t += sW1[o * 65 + c] * sH[half][c];
        t = gelu_t(t) * sW2[o];
        for (int off = 16; off; off >>= 1) t += __shfl_down_sync(0xffffffffu, t, off);
        if ((tid & 31) == 0) sred[tid >> 5] = t;
        __syncthreads();
        if ((tid & 127) == 0)
            out[(size_t)b * NN + nbase + m * 2 + half] =
                sred[half * 4] + sred[half * 4 + 1] + sred[half * 4 + 2] + sred[half * 4 + 3] + b2v;
    }
}

// ---------------- launch ----------------
extern "C" void kernel_launch(void* const* d_in, const int* in_sizes, int n_in,
                              void* d_out, int out_size) {
    (void)in_sizes; (void)n_in; (void)out_size;
    const float* x     = (const float*)d_in[0];
    const float* nodes = (const float*)d_in[2];
    const float* nw    = (const float*)d_in[3];
    const int*   edges = (const int*)d_in[4];
    const float* egw   = (const float*)d_in[5];
    const float* modes = (const float*)d_in[6];
    const float* lat   = (const float*)d_in[7];
    const float* fc0W  = (const float*)d_in[8];
    const float* fc0b  = (const float*)d_in[9];
    const float* wc    = (const float*)d_in[10];
    const float* ws    = (const float*)d_in[11];
    const float* w0    = (const float*)d_in[12];
    const float* wsW   = (const float*)d_in[13];
    const float* wsb   = (const float*)d_in[14];
    const float* gwsW  = (const float*)d_in[15];
    const float* gwsb  = (const float*)d_in[16];
    const float* fc1W  = (const float*)d_in[17];
    const float* fc1b  = (const float*)d_in[18];
    const float* fc2W  = (const float*)d_in[19];
    const float* fc2b  = (const float*)d_in[20];
    float* out = (float*)d_out;

    k_smodes<<<1, KK>>>(modes, lat);
    k_wt<<<2048, 256>>>(wc, ws);
    k_bases<<<dim3(NN, BB), KK>>>(nodes);
    k_fc0<<<4096, 256>>>(x, fc0W, fc0b);

    k_zero_cnt<<<128, 256>>>();
    k_hist<<<640, 256>>>(edges);
    k_scan<<<BB, 1024>>>();
    k_scatter<<<640, 256>>>(edges, egw);

    for (int l = 0; l < LL; ++l) {
        k_zeroA<<<64, 256>>>();
        k_a0<<<dim3(50, BB), 256>>>(nw);
        k_spectral<<<dim3(50, 4, BB), 256>>>(nw);
        k_grad<<<BB * NN / 8, 256>>>();
        k_combine<<<dim3(KK, BB), 64>>>(l, w0);
        k_wbig<<<112, 256>>>(l, gwsW, wsW, wsb, gwsb);
        k_gemm<<<dim3(250, 1, BB), 256>>>(l < LL - 1 ? 1 : 0);
    }
    k_fc12<<<dim3(250, BB), 256>>>(fc1W, fc1b, fc2W, fc2b, out);
}

// round 4
// speedup vs baseline: 1.2929x; 1.2929x over previous
#include <cuda_runtime.h>
#include <math.h>

#define BB 2
#define NN 16000
#define EE 160000
#define KK 128
#define CC 64
#define LL 3
#define AW 448      // activation row: cos(128) | sin(128) | G(128) | H(64)
#define GOFF 256
#define HOFF 384

// ---------------- device scratch (no cudaMalloc allowed) ----------------
__device__ __align__(16) float d_ACT[BB * NN * AW];          // 57.3 MB
__device__ float d_smodes[KK * 2];
__device__ __align__(16) float d_Wct[LL * KK * CC * CC];     // 12.6 MB
__device__ __align__(16) float d_Wst[LL * KK * CC * CC];     // 12.6 MB
__device__ float d_A[BB * CC * 257];                         // A_c | A_s | a0
__device__ float d_FC[BB * KK * CC];
__device__ float d_FS[BB * KK * CC];
__device__ float d_F0[BB * CC];
__device__ __align__(16) float d_Wbig[BB * AW * CC];
__device__ __align__(16) float d_bias[BB * CC];
__device__ int   d_rowptr[BB * (NN + 1)];
__device__ int   d_cursor[BB * NN];
__device__ int   d_csrc[BB * EE];
__device__ float d_cw0[BB * EE];
__device__ float d_cw1[BB * EE];

__device__ __forceinline__ float gelu_t(float x) {
    float t = tanhf(0.7978845608028654f * (x + 0.044715f * x * x * x));
    return 0.5f * x * (1.0f + t);
}

__device__ __forceinline__ unsigned f2t(float x) {
    unsigned y;
    asm("cvt.rna.tf32.f32 %0, %1;" : "=r"(y) : "f"(x));
    return y;
}

#define MMA8(c, a, bb)                                                        \
    asm volatile("mma.sync.aligned.m16n8k8.row.col.f32.tf32.tf32.f32 "       \
                 "{%0,%1,%2,%3}, {%4,%5,%6,%7}, {%8,%9}, {%0,%1,%2,%3};"     \
                 : "+f"((c)[0]), "+f"((c)[1]), "+f"((c)[2]), "+f"((c)[3])    \
                 : "r"((a)[0]), "r"((a)[1]), "r"((a)[2]), "r"((a)[3]),       \
                   "r"((bb)[0]), "r"((bb)[1]))

// ---------------- setup kernels ----------------
__global__ void k_smodes(const float* __restrict__ modes, const float* __restrict__ lat) {
    int k = threadIdx.x;
    float inv0 = 0.5f + 1.5f * (1.0f / (1.0f + expf(-lat[0])));
    float inv1 = 0.5f + 1.5f * (1.0f / (1.0f + expf(-lat[1])));
    d_smodes[k * 2 + 0] = modes[k * 2 + 0] * inv0;
    d_smodes[k * 2 + 1] = modes[k * 2 + 1] * inv1;
}

__global__ void k_wt(const float* __restrict__ wc, const float* __restrict__ ws) {
    int tot = LL * KK * CC * CC;
    for (int i = blockIdx.x * blockDim.x + threadIdx.x; i < tot; i += gridDim.x * blockDim.x) {
        int o = i & 63; int t = i >> 6;
        int ii = t & 63; t >>= 6;
        int k = t & 127; int l = t >> 7;
        int srci = (((l * CC + ii) * CC + o) * KK) + k;
        d_Wct[i] = wc[srci];
        d_Wst[i] = ws[srci];
    }
}

__global__ void k_bases(const float* __restrict__ nodes) {
    int x = blockIdx.x, b = blockIdx.y, k = threadIdx.x;
    float n0 = nodes[(b * NN + x) * 2 + 0];
    float n1 = nodes[(b * NN + x) * 2 + 1];
    float t = n0 * d_smodes[k * 2 + 0] + n1 * d_smodes[k * 2 + 1];
    float s, c;
    __sincosf(t, &s, &c);
    float* row = d_ACT + (size_t)(b * NN + x) * AW;
    row[k] = c;
    row[KK + k] = s;
}

__global__ void k_fc0(const float* __restrict__ xin, const float* __restrict__ W,
                      const float* __restrict__ bvec) {
    int tot = BB * NN * CC;
    for (int i = blockIdx.x * blockDim.x + threadIdx.x; i < tot; i += gridDim.x * blockDim.x) {
        int o = i & 63;
        int xn = i >> 6;
        const float* xr = xin + (size_t)xn * 3;
        d_ACT[(size_t)xn * AW + HOFF + o] =
            bvec[o] + W[o * 3] * xr[0] + W[o * 3 + 1] * xr[1] + W[o * 3 + 2] * xr[2];
    }
}

// ---------------- CSR build ----------------
__global__ void k_zero_cnt() {
    for (int i = blockIdx.x * blockDim.x + threadIdx.x; i < BB * NN; i += gridDim.x * blockDim.x)
        d_cursor[i] = 0;
}

__global__ void k_hist(const int* __restrict__ edges) {
    int tot = BB * EE;
    for (int i = blockIdx.x * blockDim.x + threadIdx.x; i < tot; i += gridDim.x * blockDim.x) {
        int b = i / EE;
        int tgt = edges[(size_t)i * 2];
        atomicAdd(&d_cursor[b * NN + tgt], 1);
    }
}

__global__ void k_scan() {
    int b = blockIdx.x, t = threadIdx.x;
    __shared__ int sm[1024];
    int base = t * 16;
    int loc[16];
    int run = 0;
#pragma unroll
    for (int j = 0; j < 16; ++j) {
        int idx = base + j;
        int c = (idx < NN) ? d_cursor[b * NN + idx] : 0;
        loc[j] = run;
        run += c;
    }
    sm[t] = run;
    __syncthreads();
    for (int off = 1; off < 1024; off <<= 1) {
        int v = (t >= off) ? sm[t - off] : 0;
        __syncthreads();
        sm[t] += v;
        __syncthreads();
    }
    int excl = sm[t] - run;
#pragma unroll
    for (int j = 0; j < 16; ++j) {
        int idx = base + j;
        if (idx < NN) {
            int p = excl + loc[j];
            d_rowptr[b * (NN + 1) + idx] = p;
            d_cursor[b * NN + idx] = p;
        }
    }
    if (t == 1023) d_rowptr[b * (NN + 1) + NN] = sm[1023];
}

__global__ void k_scatter(const int* __restrict__ edges, const float* __restrict__ egw) {
    int tot = BB * EE;
    for (int i = blockIdx.x * blockDim.x + threadIdx.x; i < tot; i += gridDim.x * blockDim.x) {
        int b = i / EE;
        int tgt = edges[(size_t)i * 2];
        int src = edges[(size_t)i * 2 + 1];
        int p = atomicAdd(&d_cursor[b * NN + tgt], 1);
        d_csrc[b * EE + p] = src;
        d_cw0[b * EE + p] = egw[(size_t)i * 2];
        d_cw1[b * EE + p] = egw[(size_t)i * 2 + 1];
    }
}

// ---------------- per-layer kernels ----------------
__global__ void k_zeroA() {
    for (int i = blockIdx.x * blockDim.x + threadIdx.x; i < BB * CC * 257; i += gridDim.x * blockDim.x)
        d_A[i] = 0.0f;
}

__global__ void k_a0(const float* __restrict__ nw) {
    int b = blockIdx.y, x0 = blockIdx.x * 320;
    int tid = threadIdx.x;
    int i = tid & 63, r = tid >> 6;
    float acc = 0.0f;
    for (int x = x0 + r; x < x0 + 320; x += 4)
        acc += d_ACT[(size_t)(b * NN + x) * AW + HOFF + i] * nw[b * NN + x];
    __shared__ float s[256];
    s[tid] = acc;
    __syncthreads();
    if (tid < 64)
        atomicAdd(&d_A[(b * CC + tid) * 257 + 256], s[tid] + s[tid + 64] + s[tid + 128] + s[tid + 192]);
}

// A[ch][mode] += sum_x Hw[x][ch] * basis[x][mode]  — TF32 tensor-core split-K
__global__ __launch_bounds__(256, 2) void k_spectral(const float* __restrict__ nw) {
    const int b = blockIdx.y, chk = blockIdx.x;   // 125 node-chunks of 128
    const int tid = threadIdx.x;
    const int wid = tid >> 5, lane = tid & 31;
    const int g = lane >> 2, t = lane & 3;
    const int wm = wid & 1, wn = wid >> 1;        // 2 x 4 warp grid
    __shared__ unsigned sH[32][72];               // [node][ch] (tf32 bits)
    __shared__ unsigned sBB[32][264];             // [node][mode]
    float acc[2][8][4] = {};
    const int x0 = chk * 128;
    const int nd = tid >> 3, seg = tid & 7;

    for (int cc = 0; cc < 4; ++cc) {
        __syncthreads();
        int x = x0 + cc * 32 + nd;
        const float* row = d_ACT + (size_t)(b * NN + x) * AW;
        float w = nw[b * NN + x];
        float4 h0 = *(const float4*)(row + HOFF + seg * 8);
        float4 h1 = *(const float4*)(row + HOFF + seg * 8 + 4);
        sH[nd][seg * 8 + 0] = f2t(h0.x * w); sH[nd][seg * 8 + 1] = f2t(h0.y * w);
        sH[nd][seg * 8 + 2] = f2t(h0.z * w); sH[nd][seg * 8 + 3] = f2t(h0.w * w);
        sH[nd][seg * 8 + 4] = f2t(h1.x * w); sH[nd][seg * 8 + 5] = f2t(h1.y * w);
        sH[nd][seg * 8 + 6] = f2t(h1.z * w); sH[nd][seg * 8 + 7] = f2t(h1.w * w);
#pragma unroll
        for (int j = 0; j < 8; ++j) {
            float4 bv = *(const float4*)(row + seg * 4 + j * 32);
            int c0 = seg * 4 + j * 32;
            sBB[nd][c0 + 0] = f2t(bv.x); sBB[nd][c0 + 1] = f2t(bv.y);
            sBB[nd][c0 + 2] = f2t(bv.z); sBB[nd][c0 + 3] = f2t(bv.w);
        }
        __syncthreads();
#pragma unroll
        for (int kk = 0; kk < 4; ++kk) {
            int k0 = kk * 8;
            unsigned af[2][4];
#pragma unroll
            for (int mi = 0; mi < 2; ++mi) {
                int m = wm * 32 + mi * 16;
                af[mi][0] = sH[k0 + t][m + g];
                af[mi][1] = sH[k0 + t][m + g + 8];
                af[mi][2] = sH[k0 + t + 4][m + g];
                af[mi][3] = sH[k0 + t + 4][m + g + 8];
            }
#pragma unroll
            for (int ni = 0; ni < 8; ++ni) {
                int n = wn * 64 + ni * 8;
                unsigned bf[2];
                bf[0] = sBB[k0 + t][n + g];
                bf[1] = sBB[k0 + t + 4][n + g];
                MMA8(acc[0][ni], af[0], bf);
                MMA8(acc[1][ni], af[1], bf);
            }
        }
    }
#pragma unroll
    for (int mi = 0; mi < 2; ++mi) {
        int chn = wm * 32 + mi * 16 + g;
#pragma unroll
        for (int ni = 0; ni < 8; ++ni) {
            int col = wn * 64 + ni * 8 + 2 * t;
            atomicAdd(&d_A[(b * CC + chn) * 257 + col], acc[mi][ni][0]);
            atomicAdd(&d_A[(b * CC + chn) * 257 + col + 1], acc[mi][ni][1]);
            atomicAdd(&d_A[(b * CC + chn + 8) * 257 + col], acc[mi][ni][2]);
            atomicAdd(&d_A[(b * CC + chn + 8) * 257 + col + 1], acc[mi][ni][3]);
        }
    }
}

// grad gather: one warp per node
__global__ void k_grad() {
    int w = blockIdx.x * 8 + (threadIdx.x >> 5);
    int lane = threadIdx.x & 31;
    int b = w / NN, t = w % NN;
    const float* rowt = d_ACT + (size_t)(b * NN + t) * AW;
    float ht0 = rowt[HOFF + lane], ht1 = rowt[HOFF + 32 + lane];
    int rs = d_rowptr[b * (NN + 1) + t];
    int re = d_rowptr[b * (NN + 1) + t + 1];
    float a00 = 0.f, a01 = 0.f, a10 = 0.f, a11 = 0.f;
    for (int j = rs; j < re; ++j) {
        int s = d_csrc[b * EE + j];
        float w0 = d_cw0[b * EE + j];
        float w1 = d_cw1[b * EE + j];
        const float* rows = d_ACT + (size_t)(b * NN + s) * AW;
        float dd0 = rows[HOFF + lane] - ht0;
        float dd1 = rows[HOFF + 32 + lane] - ht1;
        a00 += w0 * dd0; a01 += w1 * dd0;
        a10 += w0 * dd1; a11 += w1 * dd1;
    }
    float* g = d_ACT + (size_t)(b * NN + t) * AW + GOFF;
    *(float2*)(g + 2 * lane) = make_float2(a00, a01);
    *(float2*)(g + 64 + 2 * lane) = make_float2(a10, a11);
}

__global__ void k_combine(int l, const float* __restrict__ w0in) {
    int k = blockIdx.x, b = blockIdx.y, o = threadIdx.x;
    __shared__ float sc[64], ss[64], s0[64];
    sc[o] = d_A[(b * CC + o) * 257 + k];
    ss[o] = d_A[(b * CC + o) * 257 + 128 + k];
    if (k == 0) s0[o] = d_A[(b * CC + o) * 257 + 256];
    __syncthreads();
    const float* wc = d_Wct + ((size_t)(l * KK + k) * CC) * CC + o;
    const float* ws = d_Wst + ((size_t)(l * KK + k) * CC) * CC + o;
    float fc = 0.f, fs = 0.f;
#pragma unroll 8
    for (int i = 0; i < 64; ++i) {
        float a = sc[i], s = ss[i];
        float Wc = wc[i * CC], Wsv = ws[i * CC];
        fc += a * Wc + s * Wsv;
        fs += a * Wsv - s * Wc;
    }
    d_FC[(b * KK + k) * CC + o] = fc;
    d_FS[(b * KK + k) * CC + o] = fs;
    if (k == 0) {
        float f0 = 0.f;
        for (int i = 0; i < 64; ++i) f0 += s0[i] * w0in[(l * CC + i) * CC + o];
        d_F0[b * CC + o] = f0;
    }
}

__global__ void k_wbig(int l, const float* __restrict__ gws, const float* __restrict__ wsw,
                       const float* __restrict__ wsb, const float* __restrict__ gwsb) {
    int idx = blockIdx.x * blockDim.x + threadIdx.x;
    int tot = BB * AW * CC;
    for (int i = idx; i < tot; i += gridDim.x * blockDim.x) {
        int bb = i / (AW * CC);
        int r = i % (AW * CC);
        int j = r / CC, o = r % CC;
        float v;
        if (j < 128)      v = 2.0f * d_FC[(bb * KK + j) * CC + o];
        else if (j < 256) v = -2.0f * d_FS[(bb * KK + (j - 128)) * CC + o];
        else if (j < 384) v = gws[(l * CC + o) * 128 + (j - 256)];
        else              v = wsw[(l * CC + o) * CC + (j - 384)];
        d_Wbig[i] = v;
    }
    if (idx < BB * CC) {
        int o = idx % CC;
        d_bias[idx] = d_F0[idx] + wsb[l * CC + o] + gwsb[l * CC + o];
    }
}

// h_new = ACT(N x 448) @ Wbig(448 x 64) + bias — TF32 tensor-core GEMM
__global__ __launch_bounds__(256, 2) void k_gemm(int do_gelu) {
    const int b = blockIdx.z, nt = blockIdx.x;    // 125 tiles of 128 rows
    const int tid = threadIdx.x;
    const int wid = tid >> 5, lane = tid & 31;
    const int g = lane >> 2, t = lane & 3;
    const int wm = wid >> 1, wn = wid & 1;        // 4 x 2 warp grid
    __shared__ unsigned sA[128][36];              // [row][k]
    __shared__ unsigned sB[32][72];               // [k][n]
    float acc[2][4][4] = {};
    const float* Wb = d_Wbig + b * AW * CC;
    const size_t rowbase = (size_t)(b * NN + nt * 128);
    const int bn = tid & 63, bkg = tid >> 6;

    float4 aprf[4];
    float bprf[8];
#pragma unroll
    for (int i = 0; i < 4; ++i) {
        int idx = tid + i * 256;
        aprf[i] = *(const float4*)(d_ACT + (rowbase + (idx >> 3)) * AW + (idx & 7) * 4);
    }
#pragma unroll
    for (int j = 0; j < 8; ++j)
        bprf[j] = Wb[(bkg * 8 + j) * 64 + bn];

    for (int kc = 0; kc < 14; ++kc) {
        __syncthreads();
#pragma unroll
        for (int i = 0; i < 4; ++i) {
            int idx = tid + i * 256;
            int row = idx >> 3, seg = (idx & 7) * 4;
            sA[row][seg + 0] = f2t(aprf[i].x);
            sA[row][seg + 1] = f2t(aprf[i].y);
            sA[row][seg + 2] = f2t(aprf[i].z);
            sA[row][seg + 3] = f2t(aprf[i].w);
        }
#pragma unroll
        for (int j = 0; j < 8; ++j)
            sB[bkg * 8 + j][bn] = f2t(bprf[j]);
        __syncthreads();
        if (kc < 13) {
            int k0g = (kc + 1) * 32;
#pragma unroll
            for (int i = 0; i < 4; ++i) {
                int idx = tid + i * 256;
                aprf[i] = *(const float4*)(d_ACT + (rowbase + (idx >> 3)) * AW + k0g + (idx & 7) * 4);
            }
#pragma unroll
            for (int j = 0; j < 8; ++j)
                bprf[j] = Wb[(k0g + bkg * 8 + j) * 64 + bn];
        }
#pragma unroll
        for (int kk = 0; kk < 4; ++kk) {
            int k0 = kk * 8;
            unsigned af[2][4];
#pragma unroll
            for (int mi = 0; mi < 2; ++mi) {
                int m = wm * 32 + mi * 16;
                af[mi][0] = sA[m + g][k0 + t];
                af[mi][1] = sA[m + g + 8][k0 + t];
                af[mi][2] = sA[m + g][k0 + t + 4];
                af[mi][3] = sA[m + g + 8][k0 + t + 4];
            }
#pragma unroll
            for (int ni = 0; ni < 4; ++ni) {
                int n = wn * 32 + ni * 8;
                unsigned bf[2];
                bf[0] = sB[k0 + t][n + g];
                bf[1] = sB[k0 + t + 4][n + g];
                MMA8(acc[0][ni], af[0], bf);
                MMA8(acc[1][ni], af[1], bf);
            }
        }
    }
    const float* bias = d_bias + b * CC;
#pragma unroll
    for (int mi = 0; mi < 2; ++mi) {
        int row = nt * 128 + wm * 32 + mi * 16 + g;
#pragma unroll
        for (int ni = 0; ni < 4; ++ni) {
            int col = wn * 32 + ni * 8 + 2 * t;
            float b0v = bias[col], b1v = bias[col + 1];
            float r0 = acc[mi][ni][0] + b0v, r1 = acc[mi][ni][1] + b1v;
            float r2 = acc[mi][ni][2] + b0v, r3 = acc[mi][ni][3] + b1v;
            if (do_gelu) { r0 = gelu_t(r0); r1 = gelu_t(r1); r2 = gelu_t(r2); r3 = gelu_t(r3); }
            *(float2*)(d_ACT + (size_t)(b * NN + row) * AW + HOFF + col) = make_float2(r0, r1);
            *(float2*)(d_ACT + (size_t)(b * NN + row + 8) * AW + HOFF + col) = make_float2(r2, r3);
        }
    }
}

// out = fc2 @ gelu(fc1 @ h + b1) + b2
__global__ void k_fc12(const float* __restrict__ W1, const float* __restrict__ b1,
                       const float* __restrict__ W2, const float* __restrict__ b2,
                       float* __restrict__ out) {
    __shared__ float sW1[128 * 65];
    __shared__ float sb1[128];
    __shared__ float sW2[128];
    __shared__ float sH[2][64];
    __shared__ float sred[8];
    int tid = threadIdx.x;
    for (int i = tid; i < 128 * 64; i += 256) {
        int o = i >> 6, c = i & 63;
        sW1[o * 65 + c] = W1[i];
    }
    if (tid < 128) { sb1[tid] = b1[tid]; sW2[tid] = W2[tid]; }
    int b = blockIdx.y;
    int nbase = blockIdx.x * 64;
    int half = tid >> 7, o = tid & 127;
    float b2v = b2[0];
    for (int m = 0; m < 32; ++m) {
        __syncthreads();
        if (tid < 128) {
            int hh = tid >> 6, c = tid & 63;
            sH[hh][c] = d_ACT[(size_t)(b * NN + nbase + m * 2 + hh) * AW + HOFF + c];
        }
        __syncthreads();
        float t = sb1[o];
#pragma unroll
        for (int c = 0; c < 64; ++c) t += sW1[o * 65 + c] * sH[half][c];
        t = gelu_t(t) * sW2[o];
        for (int off = 16; off; off >>= 1) t += __shfl_down_sync(0xffffffffu, t, off);
        if ((tid & 31) == 0) sred[tid >> 5] = t;
        __syncthreads();
        if ((tid & 127) == 0)
            out[(size_t)b * NN + nbase + m * 2 + half] =
                sred[half * 4] + sred[half * 4 + 1] + sred[half * 4 + 2] + sred[half * 4 + 3] + b2v;
    }
}

// ---------------- launch ----------------
extern "C" void kernel_launch(void* const* d_in, const int* in_sizes, int n_in,
                              void* d_out, int out_size) {
    (void)in_sizes; (void)n_in; (void)out_size;
    const float* x     = (const float*)d_in[0];
    const float* nodes = (const float*)d_in[2];
    const float* nw    = (const float*)d_in[3];
    const int*   edges = (const int*)d_in[4];
    const float* egw   = (const float*)d_in[5];
    const float* modes = (const float*)d_in[6];
    const float* lat   = (const float*)d_in[7];
    const float* fc0W  = (const float*)d_in[8];
    const float* fc0b  = (const float*)d_in[9];
    const float* wc    = (const float*)d_in[10];
    const float* ws    = (const float*)d_in[11];
    const float* w0    = (const float*)d_in[12];
    const float* wsW   = (const float*)d_in[13];
    const float* wsb   = (const float*)d_in[14];
    const float* gwsW  = (const float*)d_in[15];
    const float* gwsb  = (const float*)d_in[16];
    const float* fc1W  = (const float*)d_in[17];
    const float* fc1b  = (const float*)d_in[18];
    const float* fc2W  = (const float*)d_in[19];
    const float* fc2b  = (const float*)d_in[20];
    float* out = (float*)d_out;

    k_smodes<<<1, KK>>>(modes, lat);
    k_wt<<<2048, 256>>>(wc, ws);
    k_bases<<<dim3(NN, BB), KK>>>(nodes);
    k_fc0<<<4096, 256>>>(x, fc0W, fc0b);

    k_zero_cnt<<<128, 256>>>();
    k_hist<<<640, 256>>>(edges);
    k_scan<<<BB, 1024>>>();
    k_scatter<<<640, 256>>>(edges, egw);

    for (int l = 0; l < LL; ++l) {
        k_zeroA<<<64, 256>>>();
        k_a0<<<dim3(50, BB), 256>>>(nw);
        k_spectral<<<dim3(125, BB), 256>>>(nw);
        k_grad<<<BB * NN / 8, 256>>>();
        k_combine<<<dim3(KK, BB), 64>>>(l, w0);
        k_wbig<<<112, 256>>>(l, gwsW, wsW, wsb, gwsb);
        k_gemm<<<dim3(125, 1, BB), 256>>>(l < LL - 1 ? 1 : 0);
    }
    k_fc12<<<dim3(250, BB), 256>>>(fc1W, fc1b, fc2W, fc2b, out);
}

// round 5
// speedup vs baseline: 1.4859x; 1.1492x over previous
#include <cuda_runtime.h>
#include <math.h>

#define BB 2
#define NN 16000
#define EE 160000
#define KK 128
#define CC 64
#define LL 3
#define AW 448      // activation row: cos(128) | sin(128) | G(128) | H(64)
#define GOFF 256
#define HOFF 384
#define NCH 100
#define CHN 160     // nodes per spectral chunk

// ---------------- device scratch ----------------
__device__ __align__(16) float d_ACT[BB * NN * AW];          // 57.3 MB
__device__ __align__(16) float d_Wct[LL * KK * CC * CC];     // 12.6 MB
__device__ __align__(16) float d_Wst[LL * KK * CC * CC];     // 12.6 MB
__device__ float d_A[BB * CC * 257];                         // A_c | A_s | a0
__device__ __align__(16) float d_Apart[BB * NCH * CC * 257]; // 13.2 MB partials
__device__ __align__(16) float d_Wbig[BB * AW * CC];
__device__ __align__(16) float d_bias[BB * CC];
__device__ int   d_rowptr[BB * (NN + 1)];
__device__ int   d_cursor[BB * NN];
__device__ int   d_csrc[BB * EE];
__device__ float d_cw0[BB * EE];
__device__ float d_cw1[BB * EE];

__device__ __forceinline__ float gelu_t(float x) {
    float u = 0.7978845608028654f * (x + 0.044715f * x * x * x);
    float t;
    asm("tanh.approx.f32 %0, %1;" : "=f"(t) : "f"(u));
    return 0.5f * x * (1.0f + t);
}

__device__ __forceinline__ unsigned f2t(float x) {
    unsigned y;
    asm("cvt.rna.tf32.f32 %0, %1;" : "=r"(y) : "f"(x));
    return y;
}

#define MMA8(c, a, bb)                                                        \
    asm volatile("mma.sync.aligned.m16n8k8.row.col.f32.tf32.tf32.f32 "       \
                 "{%0,%1,%2,%3}, {%4,%5,%6,%7}, {%8,%9}, {%0,%1,%2,%3};"     \
                 : "+f"((c)[0]), "+f"((c)[1]), "+f"((c)[2]), "+f"((c)[3])    \
                 : "r"((a)[0]), "r"((a)[1]), "r"((a)[2]), "r"((a)[3]),       \
                   "r"((bb)[0]), "r"((bb)[1]))

// ---------------- setup ----------------
__global__ void k_wt(const float* __restrict__ wc, const float* __restrict__ ws) {
    int tot = LL * KK * CC * CC;
    for (int i = blockIdx.x * blockDim.x + threadIdx.x; i < tot; i += gridDim.x * blockDim.x) {
        int o = i & 63; int t = i >> 6;
        int ii = t & 63; t >>= 6;
        int k = t & 127; int l = t >> 7;
        int srci = (((l * CC + ii) * CC + o) * KK) + k;
        d_Wct[i] = wc[srci];
        d_Wst[i] = ws[srci];
    }
}

// bases (sincos) + fc0, fused; smodes computed inline
__global__ void k_init(const float* __restrict__ nodes, const float* __restrict__ xin,
                       const float* __restrict__ modes, const float* __restrict__ lat,
                       const float* __restrict__ W, const float* __restrict__ bvec) {
    __shared__ float sm0[KK], sm1[KK], sW[192], sb[64];
    int b = blockIdx.y, tid = threadIdx.x;
    if (tid < 128) {
        float inv0 = 0.5f + 1.5f / (1.0f + __expf(-lat[0]));
        float inv1 = 0.5f + 1.5f / (1.0f + __expf(-lat[1]));
        sm0[tid] = modes[tid * 2 + 0] * inv0;
        sm1[tid] = modes[tid * 2 + 1] * inv1;
    }
    if (tid < 192) sW[tid] = W[tid];
    if (tid < 64) sb[tid] = bvec[tid];
    __syncthreads();
    int nbase = blockIdx.x * 128;
    int half = tid >> 7, k = tid & 127;
#pragma unroll 4
    for (int it = 0; it < 64; ++it) {
        int node = nbase + it * 2 + half;
        float n0 = nodes[(size_t)(b * NN + node) * 2 + 0];
        float n1 = nodes[(size_t)(b * NN + node) * 2 + 1];
        float tt = n0 * sm0[k] + n1 * sm1[k];
        float s, c;
        __sincosf(tt, &s, &c);
        float* row = d_ACT + (size_t)(b * NN + node) * AW;
        row[k] = c;
        row[KK + k] = s;
    }
#pragma unroll 4
    for (int it = 0; it < 32; ++it) {
        int idx = it * 256 + tid;
        int node = nbase + (idx >> 6), o = idx & 63;
        const float* xr = xin + (size_t)(b * NN + node) * 3;
        d_ACT[(size_t)(b * NN + node) * AW + HOFF + o] =
            sb[o] + sW[o * 3] * xr[0] + sW[o * 3 + 1] * xr[1] + sW[o * 3 + 2] * xr[2];
    }
}

// ---------------- CSR build ----------------
__global__ void k_zero_cnt() {
    for (int i = blockIdx.x * blockDim.x + threadIdx.x; i < BB * NN; i += gridDim.x * blockDim.x)
        d_cursor[i] = 0;
}

__global__ void k_hist(const int* __restrict__ edges) {
    int tot = BB * EE;
    for (int i = blockIdx.x * blockDim.x + threadIdx.x; i < tot; i += gridDim.x * blockDim.x) {
        int b = i / EE;
        int tgt = edges[(size_t)i * 2];
        atomicAdd(&d_cursor[b * NN + tgt], 1);
    }
}

__global__ void k_scan() {
    int b = blockIdx.x, t = threadIdx.x;
    __shared__ int sm[1024];
    int base = t * 16;
    int loc[16];
    int run = 0;
#pragma unroll
    for (int j = 0; j < 16; ++j) {
        int idx = base + j;
        int c = (idx < NN) ? d_cursor[b * NN + idx] : 0;
        loc[j] = run;
        run += c;
    }
    sm[t] = run;
    __syncthreads();
    for (int off = 1; off < 1024; off <<= 1) {
        int v = (t >= off) ? sm[t - off] : 0;
        __syncthreads();
        sm[t] += v;
        __syncthreads();
    }
    int excl = sm[t] - run;
#pragma unroll
    for (int j = 0; j < 16; ++j) {
        int idx = base + j;
        if (idx < NN) {
            int p = excl + loc[j];
            d_rowptr[b * (NN + 1) + idx] = p;
            d_cursor[b * NN + idx] = p;
        }
    }
    if (t == 1023) d_rowptr[b * (NN + 1) + NN] = sm[1023];
}

__global__ void k_scatter(const int* __restrict__ edges, const float* __restrict__ egw) {
    int tot = BB * EE;
    for (int i = blockIdx.x * blockDim.x + threadIdx.x; i < tot; i += gridDim.x * blockDim.x) {
        int b = i / EE;
        int tgt = edges[(size_t)i * 2];
        int src = edges[(size_t)i * 2 + 1];
        int p = atomicAdd(&d_cursor[b * NN + tgt], 1);
        d_csrc[b * EE + p] = src;
        d_cw0[b * EE + p] = egw[(size_t)i * 2];
        d_cw1[b * EE + p] = egw[(size_t)i * 2 + 1];
    }
}

// ---------------- per-layer kernels ----------------
// A_part[ch][mode] = sum_x Hw[x][ch] * basis[x][mode] over this chunk (no atomics)
// also a0_part[ch] = sum_x Hw[x][ch]
__global__ __launch_bounds__(256, 2) void k_spectral(const float* __restrict__ nw) {
    const int b = blockIdx.y, chk = blockIdx.x;
    const int tid = threadIdx.x;
    const int wid = tid >> 5, lane = tid & 31;
    const int g = lane >> 2, t = lane & 3;
    const int wm = wid & 1, wn = wid >> 1;        // 2 x 4 warp grid
    __shared__ unsigned sH[32][72];               // [node][ch] (tf32 bits)
    __shared__ unsigned sBB[32][264];             // [node][mode]
    float acc[2][8][4] = {};
    float a0acc = 0.0f;
    const int x0 = chk * CHN;
    const int nd = tid >> 3, seg = tid & 7;

    for (int cc = 0; cc < CHN / 32; ++cc) {
        __syncthreads();
        int x = x0 + cc * 32 + nd;
        const float* row = d_ACT + (size_t)(b * NN + x) * AW;
        float w = nw[b * NN + x];
        float4 h0 = *(const float4*)(row + HOFF + seg * 8);
        float4 h1 = *(const float4*)(row + HOFF + seg * 8 + 4);
        sH[nd][seg * 8 + 0] = f2t(h0.x * w); sH[nd][seg * 8 + 1] = f2t(h0.y * w);
        sH[nd][seg * 8 + 2] = f2t(h0.z * w); sH[nd][seg * 8 + 3] = f2t(h0.w * w);
        sH[nd][seg * 8 + 4] = f2t(h1.x * w); sH[nd][seg * 8 + 5] = f2t(h1.y * w);
        sH[nd][seg * 8 + 6] = f2t(h1.z * w); sH[nd][seg * 8 + 7] = f2t(h1.w * w);
#pragma unroll
        for (int j = 0; j < 8; ++j) {
            float4 bv = *(const float4*)(row + seg * 4 + j * 32);
            int c0 = seg * 4 + j * 32;
            sBB[nd][c0 + 0] = f2t(bv.x); sBB[nd][c0 + 1] = f2t(bv.y);
            sBB[nd][c0 + 2] = f2t(bv.z); sBB[nd][c0 + 3] = f2t(bv.w);
        }
        __syncthreads();
        if (tid < 64) {
#pragma unroll
            for (int n2 = 0; n2 < 32; ++n2)
                a0acc += __uint_as_float(sH[n2][tid]);
        }
#pragma unroll
        for (int kk = 0; kk < 4; ++kk) {
            int k0 = kk * 8;
            unsigned af[2][4];
#pragma unroll
            for (int mi = 0; mi < 2; ++mi) {
                int m = wm * 32 + mi * 16;
                af[mi][0] = sH[k0 + t][m + g];
                af[mi][1] = sH[k0 + t][m + g + 8];
                af[mi][2] = sH[k0 + t + 4][m + g];
                af[mi][3] = sH[k0 + t + 4][m + g + 8];
            }
#pragma unroll
            for (int ni = 0; ni < 8; ++ni) {
                int n = wn * 64 + ni * 8;
                unsigned bf[2];
                bf[0] = sBB[k0 + t][n + g];
                bf[1] = sBB[k0 + t + 4][n + g];
                MMA8(acc[0][ni], af[0], bf);
                MMA8(acc[1][ni], af[1], bf);
            }
        }
    }
    float* base = d_Apart + (size_t)(b * NCH + chk) * CC * 257;
#pragma unroll
    for (int mi = 0; mi < 2; ++mi) {
        int chn = wm * 32 + mi * 16 + g;
#pragma unroll
        for (int ni = 0; ni < 8; ++ni) {
            int col = wn * 64 + ni * 8 + 2 * t;
            base[chn * 257 + col]           = acc[mi][ni][0];
            base[chn * 257 + col + 1]       = acc[mi][ni][1];
            base[(chn + 8) * 257 + col]     = acc[mi][ni][2];
            base[(chn + 8) * 257 + col + 1] = acc[mi][ni][3];
        }
    }
    if (tid < 64) base[tid * 257 + 256] = a0acc;
}

__global__ void k_reduceA() {
    int b = blockIdx.y;
    int i = blockIdx.x * 512 + threadIdx.x;
    if (i >= CC * 257) return;
    const float* p = d_Apart + (size_t)b * NCH * CC * 257 + i;
    float s = 0.0f;
#pragma unroll 4
    for (int c = 0; c < NCH; ++c) s += p[(size_t)c * CC * 257];
    d_A[b * CC * 257 + i] = s;
}

// grad gather: one warp per node
__global__ void k_grad() {
    int w = blockIdx.x * 8 + (threadIdx.x >> 5);
    int lane = threadIdx.x & 31;
    int b = w / NN, t = w % NN;
    const float* rowt = d_ACT + (size_t)(b * NN + t) * AW;
    float ht0 = rowt[HOFF + lane], ht1 = rowt[HOFF + 32 + lane];
    int rs = d_rowptr[b * (NN + 1) + t];
    int re = d_rowptr[b * (NN + 1) + t + 1];
    float a00 = 0.f, a01 = 0.f, a10 = 0.f, a11 = 0.f;
    for (int j = rs; j < re; ++j) {
        int s = d_csrc[b * EE + j];
        float w0 = d_cw0[b * EE + j];
        float w1 = d_cw1[b * EE + j];
        const float* rows = d_ACT + (size_t)(b * NN + s) * AW;
        float dd0 = rows[HOFF + lane] - ht0;
        float dd1 = rows[HOFF + 32 + lane] - ht1;
        a00 += w0 * dd0; a01 += w1 * dd0;
        a10 += w0 * dd1; a11 += w1 * dd1;
    }
    float* g = d_ACT + (size_t)(b * NN + t) * AW + GOFF;
    *(float2*)(g + 2 * lane) = make_float2(a00, a01);
    *(float2*)(g + 64 + 2 * lane) = make_float2(a10, a11);
}

// combine (f_c,f_s per mode) + build Wbig + bias in one kernel
__global__ void k_combine(int l, const float* __restrict__ w0in,
                          const float* __restrict__ gws, const float* __restrict__ wsw,
                          const float* __restrict__ wsb, const float* __restrict__ gwsb) {
    int k = blockIdx.x, b = blockIdx.y, o = threadIdx.x;
    if (k < 128) {
        __shared__ float sc[64], ss[64];
        sc[o] = d_A[(b * CC + o) * 257 + k];
        ss[o] = d_A[(b * CC + o) * 257 + 128 + k];
        __syncthreads();
        const float* wc = d_Wct + (size_t)(l * KK + k) * CC * CC + o;
        const float* ws = d_Wst + (size_t)(l * KK + k) * CC * CC + o;
        float fc = 0.f, fs = 0.f;
#pragma unroll 8
        for (int i = 0; i < 64; ++i) {
            float a = sc[i], s = ss[i];
            float Wc = wc[i * CC], Wsv = ws[i * CC];
            fc += a * Wc + s * Wsv;
            fs += a * Wsv - s * Wc;
        }
        d_Wbig[(size_t)(b * AW + k) * CC + o] = 2.0f * fc;
        d_Wbig[(size_t)(b * AW + 128 + k) * CC + o] = -2.0f * fs;
    } else if (k < 130) {
        int j0 = (k - 128) * 64;
        for (int r = 0; r < 64; ++r)
            d_Wbig[(size_t)(b * AW + 256 + j0 + r) * CC + o] = gws[(l * CC + o) * 128 + j0 + r];
    } else {
        for (int r = 0; r < 64; ++r)
            d_Wbig[(size_t)(b * AW + 384 + r) * CC + o] = wsw[(l * CC + o) * CC + r];
        float f0 = 0.f;
        for (int i = 0; i < 64; ++i)
            f0 += d_A[(b * CC + i) * 257 + 256] * w0in[(l * CC + i) * CC + o];
        d_bias[b * CC + o] = f0 + wsb[l * CC + o] + gwsb[l * CC + o];
    }
}

// h_new = ACT(N x 448) @ Wbig(448 x 64) + bias — TF32 tensor-core GEMM
__global__ __launch_bounds__(256, 2) void k_gemm(int do_gelu) {
    const int b = blockIdx.z, nt = blockIdx.x;
    const int tid = threadIdx.x;
    const int wid = tid >> 5, lane = tid & 31;
    const int g = lane >> 2, t = lane & 3;
    const int wm = wid >> 1, wn = wid & 1;
    __shared__ unsigned sA[128][36];
    __shared__ unsigned sB[32][72];
    float acc[2][4][4] = {};
    const float* Wb = d_Wbig + (size_t)b * AW * CC;
    const size_t rowbase = (size_t)(b * NN + nt * 128);
    const int bn = tid & 63, bkg = tid >> 6;

    float4 aprf[4];
    float bprf[8];
#pragma unroll
    for (int i = 0; i < 4; ++i) {
        int idx = tid + i * 256;
        aprf[i] = *(const float4*)(d_ACT + (rowbase + (idx >> 3)) * AW + (idx & 7) * 4);
    }
#pragma unroll
    for (int j = 0; j < 8; ++j)
        bprf[j] = Wb[(bkg * 8 + j) * 64 + bn];

    for (int kc = 0; kc < 14; ++kc) {
        __syncthreads();
#pragma unroll
        for (int i = 0; i < 4; ++i) {
            int idx = tid + i * 256;
            int row = idx >> 3, seg = (idx & 7) * 4;
            sA[row][seg + 0] = f2t(aprf[i].x);
            sA[row][seg + 1] = f2t(aprf[i].y);
            sA[row][seg + 2] = f2t(aprf[i].z);
            sA[row][seg + 3] = f2t(aprf[i].w);
        }
#pragma unroll
        for (int j = 0; j < 8; ++j)
            sB[bkg * 8 + j][bn] = f2t(bprf[j]);
        __syncthreads();
        if (kc < 13) {
            int k0g = (kc + 1) * 32;
#pragma unroll
            for (int i = 0; i < 4; ++i) {
                int idx = tid + i * 256;
                aprf[i] = *(const float4*)(d_ACT + (rowbase + (idx >> 3)) * AW + k0g + (idx & 7) * 4);
            }
#pragma unroll
            for (int j = 0; j < 8; ++j)
                bprf[j] = Wb[(k0g + bkg * 8 + j) * 64 + bn];
        }
#pragma unroll
        for (int kk = 0; kk < 4; ++kk) {
            int k0 = kk * 8;
            unsigned af[2][4];
#pragma unroll
            for (int mi = 0; mi < 2; ++mi) {
                int m = wm * 32 + mi * 16;
                af[mi][0] = sA[m + g][k0 + t];
                af[mi][1] = sA[m + g + 8][k0 + t];
                af[mi][2] = sA[m + g][k0 + t + 4];
                af[mi][3] = sA[m + g + 8][k0 + t + 4];
            }
#pragma unroll
            for (int ni = 0; ni < 4; ++ni) {
                int n = wn * 32 + ni * 8;
                unsigned bf[2];
                bf[0] = sB[k0 + t][n + g];
                bf[1] = sB[k0 + t + 4][n + g];
                MMA8(acc[0][ni], af[0], bf);
                MMA8(acc[1][ni], af[1], bf);
            }
        }
    }
    const float* bias = d_bias + b * CC;
#pragma unroll
    for (int mi = 0; mi < 2; ++mi) {
        int row = nt * 128 + wm * 32 + mi * 16 + g;
#pragma unroll
        for (int ni = 0; ni < 4; ++ni) {
            int col = wn * 32 + ni * 8 + 2 * t;
            float b0v = bias[col], b1v = bias[col + 1];
            float r0 = acc[mi][ni][0] + b0v, r1 = acc[mi][ni][1] + b1v;
            float r2 = acc[mi][ni][2] + b0v, r3 = acc[mi][ni][3] + b1v;
            if (do_gelu) { r0 = gelu_t(r0); r1 = gelu_t(r1); r2 = gelu_t(r2); r3 = gelu_t(r3); }
            *(float2*)(d_ACT + (size_t)(b * NN + row) * AW + HOFF + col) = make_float2(r0, r1);
            *(float2*)(d_ACT + (size_t)(b * NN + row + 8) * AW + HOFF + col) = make_float2(r2, r3);
        }
    }
}

// out = fc2 @ gelu(fc1 @ h + b1) + b2
__global__ void k_fc12(const float* __restrict__ W1, const float* __restrict__ b1,
                       const float* __restrict__ W2, const float* __restrict__ b2,
                       float* __restrict__ out) {
    __shared__ float sW1[128 * 65];
    __shared__ float sb1[128];
    __shared__ float sW2[128];
    __shared__ float sH[2][64];
    __shared__ float sred[8];
    int tid = threadIdx.x;
    for (int i = tid; i < 128 * 64; i += 256) {
        int o = i >> 6, c = i & 63;
        sW1[o * 65 + c] = W1[i];
    }
    if (tid < 128) { sb1[tid] = b1[tid]; sW2[tid] = W2[tid]; }
    int b = blockIdx.y;
    int nbase = blockIdx.x * 64;
    int half = tid >> 7, o = tid & 127;
    float b2v = b2[0];
    for (int m = 0; m < 32; ++m) {
        __syncthreads();
        if (tid < 128) {
            int hh = tid >> 6, c = tid & 63;
            sH[hh][c] = d_ACT[(size_t)(b * NN + nbase + m * 2 + hh) * AW + HOFF + c];
        }
        __syncthreads();
        float t = sb1[o];
#pragma unroll
        for (int c = 0; c < 64; ++c) t += sW1[o * 65 + c] * sH[half][c];
        t = gelu_t(t) * sW2[o];
        for (int off = 16; off; off >>= 1) t += __shfl_down_sync(0xffffffffu, t, off);
        if ((tid & 31) == 0) sred[tid >> 5] = t;
        __syncthreads();
        if ((tid & 127) == 0)
            out[(size_t)b * NN + nbase + m * 2 + half] =
                sred[half * 4] + sred[half * 4 + 1] + sred[half * 4 + 2] + sred[half * 4 + 3] + b2v;
    }
}

// ---------------- launch ----------------
extern "C" void kernel_launch(void* const* d_in, const int* in_sizes, int n_in,
                              void* d_out, int out_size) {
    (void)in_sizes; (void)n_in; (void)out_size;
    const float* x     = (const float*)d_in[0];
    const float* nodes = (const float*)d_in[2];
    const float* nw    = (const float*)d_in[3];
    const int*   edges = (const int*)d_in[4];
    const float* egw   = (const float*)d_in[5];
    const float* modes = (const float*)d_in[6];
    const float* lat   = (const float*)d_in[7];
    const float* fc0W  = (const float*)d_in[8];
    const float* fc0b  = (const float*)d_in[9];
    const float* wc    = (const float*)d_in[10];
    const float* ws    = (const float*)d_in[11];
    const float* w0    = (const float*)d_in[12];
    const float* wsW   = (const float*)d_in[13];
    const float* wsb   = (const float*)d_in[14];
    const float* gwsW  = (const float*)d_in[15];
    const float* gwsb  = (const float*)d_in[16];
    const float* fc1W  = (const float*)d_in[17];
    const float* fc1b  = (const float*)d_in[18];
    const float* fc2W  = (const float*)d_in[19];
    const float* fc2b  = (const float*)d_in[20];
    float* out = (float*)d_out;

    k_wt<<<2048, 256>>>(wc, ws);
    k_init<<<dim3(125, BB), 256>>>(nodes, x, modes, lat, fc0W, fc0b);

    k_zero_cnt<<<128, 256>>>();
    k_hist<<<640, 256>>>(edges);
    k_scan<<<BB, 1024>>>();
    k_scatter<<<640, 256>>>(edges, egw);

    for (int l = 0; l < LL; ++l) {
        k_spectral<<<dim3(NCH, BB), 256>>>(nw);
        k_reduceA<<<dim3(33, BB), 512>>>();
        k_grad<<<BB * NN / 8, 256>>>();
        k_combine<<<dim3(131, BB), 64>>>(l, w0, gwsW, wsW, wsb, gwsb);
        k_gemm<<<dim3(125, 1, BB), 256>>>(l < LL - 1 ? 1 : 0);
    }
    k_fc12<<<dim3(250, BB), 256>>>(fc1W, fc1b, fc2W, fc2b, out);
}

// round 6
// speedup vs baseline: 2.1295x; 1.4331x over previous
#include <cuda_runtime.h>
#include <math.h>

#define BB 2
#define NN 16000
#define EE 160000
#define KK 128
#define CC 64
#define LL 3
#define AW 448      // activation row: cos(128) | sin(128) | G(128) | H(64)
#define GOFF 256
#define HOFF 384
#define NCH 125
#define CHN 128
#define APC (257 * 64)

// ---------------- device scratch ----------------
__device__ __align__(16) float d_ACT[BB * NN * AW];          // 57.3 MB
__device__ __align__(16) float d_Wct[LL * KK * CC * CC];
__device__ __align__(16) float d_Wst[LL * KK * CC * CC];
__device__ __align__(16) float d_Apart[BB * NCH * APC];      // [b][chunk][col][ch]
__device__ __align__(16) float d_Wbig[BB * AW * CC];
__device__ __align__(16) float d_bias[BB * CC];
__device__ int   d_rowptr[BB * (NN + 1)];
__device__ int   d_cursor[BB * NN];
__device__ int   d_csrc[BB * EE];
__device__ float d_cw0[BB * EE];
__device__ float d_cw1[BB * EE];

__device__ __forceinline__ float gelu_t(float x) {
    float u = 0.7978845608028654f * (x + 0.044715f * x * x * x);
    float t;
    asm("tanh.approx.f32 %0, %1;" : "=f"(t) : "f"(u));
    return 0.5f * x * (1.0f + t);
}

__device__ __forceinline__ unsigned f2t(float x) {
    unsigned y;
    asm("cvt.rna.tf32.f32 %0, %1;" : "=r"(y) : "f"(x));
    return y;
}

#define MMA8(c, a, bb)                                                        \
    asm volatile("mma.sync.aligned.m16n8k8.row.col.f32.tf32.tf32.f32 "       \
                 "{%0,%1,%2,%3}, {%4,%5,%6,%7}, {%8,%9}, {%0,%1,%2,%3};"     \
                 : "+f"((c)[0]), "+f"((c)[1]), "+f"((c)[2]), "+f"((c)[3])    \
                 : "r"((a)[0]), "r"((a)[1]), "r"((a)[2]), "r"((a)[3]),       \
                   "r"((bb)[0]), "r"((bb)[1]))

// ---------------- fat setup: weight transpose + bases/fc0 + cursor zero ----------------
__global__ void k_setup(const float* __restrict__ nodes, const float* __restrict__ xin,
                        const float* __restrict__ modes, const float* __restrict__ lat,
                        const float* __restrict__ W, const float* __restrict__ bvec,
                        const float* __restrict__ wc, const float* __restrict__ ws) {
    __shared__ float sm0[KK], sm1[KK], sW[192], sb[64];
    int bid = blockIdx.x, tid = threadIdx.x;
    if (bid < 250) {
        int b = bid / 125;
        int nbase = (bid % 125) * 128;
        if (tid < 128) {
            float inv0 = 0.5f + 1.5f / (1.0f + __expf(-lat[0]));
            float inv1 = 0.5f + 1.5f / (1.0f + __expf(-lat[1]));
            sm0[tid] = modes[tid * 2 + 0] * inv0;
            sm1[tid] = modes[tid * 2 + 1] * inv1;
        }
        if (tid < 192) sW[tid] = W[tid];
        if (tid < 64) sb[tid] = bvec[tid];
        __syncthreads();
        int half = tid >> 7, k = tid & 127;
#pragma unroll 4
        for (int it = 0; it < 64; ++it) {
            int node = nbase + it * 2 + half;
            float n0 = nodes[(size_t)(b * NN + node) * 2 + 0];
            float n1 = nodes[(size_t)(b * NN + node) * 2 + 1];
            float tt = n0 * sm0[k] + n1 * sm1[k];
            float s, c;
            __sincosf(tt, &s, &c);
            float* row = d_ACT + (size_t)(b * NN + node) * AW;
            row[k] = c;
            row[KK + k] = s;
        }
#pragma unroll 4
        for (int it = 0; it < 32; ++it) {
            int idx = it * 256 + tid;
            int node = nbase + (idx >> 6), o = idx & 63;
            const float* xr = xin + (size_t)(b * NN + node) * 3;
            d_ACT[(size_t)(b * NN + node) * AW + HOFF + o] =
                sb[o] + sW[o * 3] * xr[0] + sW[o * 3 + 1] * xr[1] + sW[o * 3 + 2] * xr[2];
        }
    } else if (bid < 762) {
        int tot = LL * KK * CC * CC;
        for (int i = (bid - 250) * 256 + tid; i < tot; i += 512 * 256) {
            int o = i & 63; int t = i >> 6;
            int ii = t & 63; t >>= 6;
            int k = t & 127; int l = t >> 7;
            int srci = (((l * CC + ii) * CC + o) * KK) + k;
            d_Wct[i] = wc[srci];
            d_Wst[i] = ws[srci];
        }
    } else {
        for (int i = (bid - 762) * 256 + tid; i < BB * NN; i += 32 * 256)
            d_cursor[i] = 0;
    }
}

// ---------------- CSR build ----------------
__global__ void k_hist(const int* __restrict__ edges) {
    int tot = BB * EE;
    for (int i = blockIdx.x * blockDim.x + threadIdx.x; i < tot; i += gridDim.x * blockDim.x) {
        int b = i / EE;
        int2 e = ((const int2*)edges)[i];
        atomicAdd(&d_cursor[b * NN + e.x], 1);
    }
}

__global__ void k_scan() {
    int b = blockIdx.x, t = threadIdx.x;
    __shared__ int sm[1024];
    int base = t * 16;
    int loc[16];
    int run = 0;
#pragma unroll
    for (int j = 0; j < 16; ++j) {
        int idx = base + j;
        int c = (idx < NN) ? d_cursor[b * NN + idx] : 0;
        loc[j] = run;
        run += c;
    }
    sm[t] = run;
    __syncthreads();
    for (int off = 1; off < 1024; off <<= 1) {
        int v = (t >= off) ? sm[t - off] : 0;
        __syncthreads();
        sm[t] += v;
        __syncthreads();
    }
    int excl = sm[t] - run;
#pragma unroll
    for (int j = 0; j < 16; ++j) {
        int idx = base + j;
        if (idx < NN) {
            int p = excl + loc[j];
            d_rowptr[b * (NN + 1) + idx] = p;
            d_cursor[b * NN + idx] = p;
        }
    }
    if (t == 1023) d_rowptr[b * (NN + 1) + NN] = sm[1023];
}

__global__ void k_scatter(const int* __restrict__ edges, const float* __restrict__ egw) {
    int tot = BB * EE;
    for (int i = blockIdx.x * blockDim.x + threadIdx.x; i < tot; i += gridDim.x * blockDim.x) {
        int b = i / EE;
        int2 e = ((const int2*)edges)[i];
        int p = atomicAdd(&d_cursor[b * NN + e.x], 1);
        d_csrc[b * EE + p] = e.y;
        d_cw0[b * EE + p] = egw[(size_t)i * 2];
        d_cw1[b * EE + p] = egw[(size_t)i * 2 + 1];
    }
}

// ---------------- per-layer kernels ----------------
// A_part[col][ch] = sum_x basis[x][col] * Hw[x][ch]  over this chunk; col 256 = a0
__global__ __launch_bounds__(256, 2) void k_spectral(const float* __restrict__ nw) {
    const int b = blockIdx.y, chk = blockIdx.x;
    const int tid = threadIdx.x;
    const int wid = tid >> 5, lane = tid & 31;
    const int g = lane >> 2, t = lane & 3;
    const int wm = wid & 1, wn = wid >> 1;        // 2(ch) x 4(col) warp grid
    __shared__ unsigned sH[32][72];
    __shared__ unsigned sBB[32][264];
    float acc[2][8][4] = {};
    float a0acc = 0.0f;
    const int x0 = chk * CHN;
    const int nd = tid >> 3, seg = tid & 7;

    for (int cc = 0; cc < CHN / 32; ++cc) {
        __syncthreads();
        int x = x0 + cc * 32 + nd;
        const float* row = d_ACT + (size_t)(b * NN + x) * AW;
        float w = nw[b * NN + x];
        float4 h0 = *(const float4*)(row + HOFF + seg * 8);
        float4 h1 = *(const float4*)(row + HOFF + seg * 8 + 4);
        *(uint4*)&sH[nd][seg * 8] =
            make_uint4(f2t(h0.x * w), f2t(h0.y * w), f2t(h0.z * w), f2t(h0.w * w));
        *(uint4*)&sH[nd][seg * 8 + 4] =
            make_uint4(f2t(h1.x * w), f2t(h1.y * w), f2t(h1.z * w), f2t(h1.w * w));
#pragma unroll
        for (int j = 0; j < 8; ++j) {
            float4 bv = *(const float4*)(row + seg * 4 + j * 32);
            *(uint4*)&sBB[nd][seg * 4 + j * 32] =
                make_uint4(f2t(bv.x), f2t(bv.y), f2t(bv.z), f2t(bv.w));
        }
        __syncthreads();
        if (tid < 64) {
#pragma unroll
            for (int n2 = 0; n2 < 32; ++n2)
                a0acc += __uint_as_float(sH[n2][tid]);
        }
#pragma unroll
        for (int kk = 0; kk < 4; ++kk) {
            int k0 = kk * 8;
            unsigned af[2][4];
#pragma unroll
            for (int mi = 0; mi < 2; ++mi) {
                int m = wm * 32 + mi * 16;
                af[mi][0] = sH[k0 + t][m + g];
                af[mi][1] = sH[k0 + t][m + g + 8];
                af[mi][2] = sH[k0 + t + 4][m + g];
                af[mi][3] = sH[k0 + t + 4][m + g + 8];
            }
#pragma unroll
            for (int ni = 0; ni < 8; ++ni) {
                int n = wn * 64 + ni * 8;
                unsigned bf[2];
                bf[0] = sBB[k0 + t][n + g];
                bf[1] = sBB[k0 + t + 4][n + g];
                MMA8(acc[0][ni], af[0], bf);
                MMA8(acc[1][ni], af[1], bf);
            }
        }
    }
    float* base = d_Apart + (size_t)(b * NCH + chk) * APC;
#pragma unroll
    for (int mi = 0; mi < 2; ++mi) {
        int chn = wm * 32 + mi * 16 + g;
#pragma unroll
        for (int ni = 0; ni < 8; ++ni) {
            int col = wn * 64 + ni * 8 + 2 * t;
            base[col * 64 + chn]             = acc[mi][ni][0];
            base[(col + 1) * 64 + chn]       = acc[mi][ni][1];
            base[col * 64 + chn + 8]         = acc[mi][ni][2];
            base[(col + 1) * 64 + chn + 8]   = acc[mi][ni][3];
        }
    }
    if (tid < 64) base[256 * 64 + tid] = a0acc;
}

// grad gather: one warp per node, 4-edge batches for MLP
__global__ void k_grad() {
    int w = blockIdx.x * 8 + (threadIdx.x >> 5);
    int lane = threadIdx.x & 31;
    int b = w / NN, t = w % NN;
    const float* rowt = d_ACT + (size_t)(b * NN + t) * AW;
    float ht0 = rowt[HOFF + lane], ht1 = rowt[HOFF + 32 + lane];
    int rs = d_rowptr[b * (NN + 1) + t];
    int re = d_rowptr[b * (NN + 1) + t + 1];
    const int* csrc = d_csrc + b * EE;
    const float* cw0 = d_cw0 + b * EE;
    const float* cw1 = d_cw1 + b * EE;
    float a00 = 0.f, a01 = 0.f, a10 = 0.f, a11 = 0.f;
    int j = rs;
    for (; j + 4 <= re; j += 4) {
        int s0 = csrc[j], s1 = csrc[j + 1], s2 = csrc[j + 2], s3 = csrc[j + 3];
        float w00 = cw0[j], w01 = cw0[j + 1], w02 = cw0[j + 2], w03 = cw0[j + 3];
        float w10 = cw1[j], w11 = cw1[j + 1], w12 = cw1[j + 2], w13 = cw1[j + 3];
        const float* r0 = d_ACT + (size_t)(b * NN + s0) * AW + HOFF;
        const float* r1 = d_ACT + (size_t)(b * NN + s1) * AW + HOFF;
        const float* r2 = d_ACT + (size_t)(b * NN + s2) * AW + HOFF;
        const float* r3 = d_ACT + (size_t)(b * NN + s3) * AW + HOFF;
        float p00 = r0[lane], p01 = r0[32 + lane];
        float p10 = r1[lane], p11 = r1[32 + lane];
        float p20 = r2[lane], p21 = r2[32 + lane];
        float p30 = r3[lane], p31 = r3[32 + lane];
        float d0 = p00 - ht0, e0 = p01 - ht1;
        float d1 = p10 - ht0, e1 = p11 - ht1;
        float d2 = p20 - ht0, e2 = p21 - ht1;
        float d3 = p30 - ht0, e3 = p31 - ht1;
        a00 += w00 * d0 + w01 * d1 + w02 * d2 + w03 * d3;
        a01 += w10 * d0 + w11 * d1 + w12 * d2 + w13 * d3;
        a10 += w00 * e0 + w01 * e1 + w02 * e2 + w03 * e3;
        a11 += w10 * e0 + w11 * e1 + w12 * e2 + w13 * e3;
    }
    for (; j < re; ++j) {
        int s = csrc[j];
        float w0 = cw0[j], w1 = cw1[j];
        const float* rr = d_ACT + (size_t)(b * NN + s) * AW + HOFF;
        float dd0 = rr[lane] - ht0;
        float dd1 = rr[32 + lane] - ht1;
        a00 += w0 * dd0; a01 += w1 * dd0;
        a10 += w0 * dd1; a11 += w1 * dd1;
    }
    float* g = d_ACT + (size_t)(b * NN + t) * AW + GOFF;
    *(float2*)(g + 2 * lane) = make_float2(a00, a01);
    *(float2*)(g + 64 + 2 * lane) = make_float2(a10, a11);
}

// fused: reduce Apart over chunks + f_c/f_s combine + build Wbig + bias
__global__ void k_combine(int l, const float* __restrict__ w0in,
                          const float* __restrict__ gws, const float* __restrict__ wsw,
                          const float* __restrict__ wsb, const float* __restrict__ gwsb) {
    const int k = blockIdx.x, b = blockIdx.y;
    const int tid = threadIdx.x;
    const int o = tid & 63, q = tid >> 6;
    const float* Ap = d_Apart + (size_t)b * NCH * APC;
    __shared__ float red[4][64], red2[4][64];
    __shared__ float sc[64], ss[64];
    if (k < 128) {
        float pc = 0.f, ps = 0.f;
#pragma unroll 4
        for (int c = q; c < NCH; c += 4) {
            const float* pch = Ap + (size_t)c * APC;
            pc += pch[k * 64 + o];
            ps += pch[(128 + k) * 64 + o];
        }
        red[q][o] = pc; red2[q][o] = ps;
        __syncthreads();
        if (tid < 64) {
            sc[o] = red[0][o] + red[1][o] + red[2][o] + red[3][o];
            ss[o] = red2[0][o] + red2[1][o] + red2[2][o] + red2[3][o];
        }
        __syncthreads();
        const float* wc = d_Wct + (size_t)(l * KK + k) * CC * CC;
        const float* ws = d_Wst + (size_t)(l * KK + k) * CC * CC;
        float fc = 0.f, fs = 0.f;
#pragma unroll 4
        for (int i = q * 16; i < q * 16 + 16; ++i) {
            float a = sc[i], s = ss[i];
            float Wc = wc[i * CC + o], Wsv = ws[i * CC + o];
            fc += a * Wc + s * Wsv;
            fs += a * Wsv - s * Wc;
        }
        __syncthreads();
        red[q][o] = fc; red2[q][o] = fs;
        __syncthreads();
        if (tid < 64) {
            float fct = red[0][o] + red[1][o] + red[2][o] + red[3][o];
            float fst = red2[0][o] + red2[1][o] + red2[2][o] + red2[3][o];
            d_Wbig[(size_t)(b * AW + k) * CC + o] = 2.0f * fct;
            d_Wbig[(size_t)(b * AW + 128 + k) * CC + o] = -2.0f * fst;
        }
    } else if (k < 130) {
        int j0 = (k - 128) * 64;
        for (int idx = tid; idx < 64 * 64; idx += 256) {
            int jr = idx >> 6, oo = idx & 63;
            d_Wbig[(size_t)(b * AW + 256 + j0 + jr) * CC + oo] =
                gws[(l * CC + oo) * 128 + j0 + jr];
        }
    } else {
        for (int idx = tid; idx < 64 * 64; idx += 256) {
            int jr = idx >> 6, oo = idx & 63;
            d_Wbig[(size_t)(b * AW + 384 + jr) * CC + oo] = wsw[(l * CC + oo) * CC + jr];
        }
        float pa = 0.f;
        for (int c = q; c < NCH; c += 4)
            pa += Ap[(size_t)c * APC + 256 * 64 + o];
        red[q][o] = pa;
        __syncthreads();
        if (tid < 64) sc[o] = red[0][o] + red[1][o] + red[2][o] + red[3][o];
        __syncthreads();
        if (tid < 64) {
            float f0 = 0.f;
#pragma unroll 8
            for (int i = 0; i < 64; ++i)
                f0 += sc[i] * w0in[(l * CC + i) * CC + o];
            d_bias[b * CC + o] = f0 + wsb[l * CC + o] + gwsb[l * CC + o];
        }
    }
}

// h_new = ACT(N x 448) @ Wbig(448 x 64) + bias — TF32 tensor-core GEMM
__global__ __launch_bounds__(256, 2) void k_gemm(int do_gelu) {
    const int b = blockIdx.z, nt = blockIdx.x;
    const int tid = threadIdx.x;
    const int wid = tid >> 5, lane = tid & 31;
    const int g = lane >> 2, t = lane & 3;
    const int wm = wid >> 1, wn = wid & 1;
    __shared__ unsigned sA[128][36];
    __shared__ unsigned sB[32][72];
    float acc[2][4][4] = {};
    const float* Wb = d_Wbig + (size_t)b * AW * CC;
    const size_t rowbase = (size_t)(b * NN + nt * 128);
    const int bn = tid & 63, bkg = tid >> 6;

    float4 aprf[4];
    float bprf[8];
#pragma unroll
    for (int i = 0; i < 4; ++i) {
        int idx = tid + i * 256;
        aprf[i] = *(const float4*)(d_ACT + (rowbase + (idx >> 3)) * AW + (idx & 7) * 4);
    }
#pragma unroll
    for (int j = 0; j < 8; ++j)
        bprf[j] = Wb[(bkg * 8 + j) * 64 + bn];

    for (int kc = 0; kc < 14; ++kc) {
        __syncthreads();
#pragma unroll
        for (int i = 0; i < 4; ++i) {
            int idx = tid + i * 256;
            int row = idx >> 3, seg = (idx & 7) * 4;
            *(uint4*)&sA[row][seg] =
                make_uint4(f2t(aprf[i].x), f2t(aprf[i].y), f2t(aprf[i].z), f2t(aprf[i].w));
        }
#pragma unroll
        for (int j = 0; j < 8; ++j)
            sB[bkg * 8 + j][bn] = f2t(bprf[j]);
        __syncthreads();
        if (kc < 13) {
            int k0g = (kc + 1) * 32;
#pragma unroll
            for (int i = 0; i < 4; ++i) {
                int idx = tid + i * 256;
                aprf[i] = *(const float4*)(d_ACT + (rowbase + (idx >> 3)) * AW + k0g + (idx & 7) * 4);
            }
#pragma unroll
            for (int j = 0; j < 8; ++j)
                bprf[j] = Wb[(k0g + bkg * 8 + j) * 64 + bn];
        }
#pragma unroll
        for (int kk = 0; kk < 4; ++kk) {
            int k0 = kk * 8;
            unsigned af[2][4];
#pragma unroll
            for (int mi = 0; mi < 2; ++mi) {
                int m = wm * 32 + mi * 16;
                af[mi][0] = sA[m + g][k0 + t];
                af[mi][1] = sA[m + g + 8][k0 + t];
                af[mi][2] = sA[m + g][k0 + t + 4];
                af[mi][3] = sA[m + g + 8][k0 + t + 4];
            }
#pragma unroll
            for (int ni = 0; ni < 4; ++ni) {
                int n = wn * 32 + ni * 8;
                unsigned bf[2];
                bf[0] = sB[k0 + t][n + g];
                bf[1] = sB[k0 + t + 4][n + g];
                MMA8(acc[0][ni], af[0], bf);
                MMA8(acc[1][ni], af[1], bf);
            }
        }
    }
    const float* bias = d_bias + b * CC;
#pragma unroll
    for (int mi = 0; mi < 2; ++mi) {
        int row = nt * 128 + wm * 32 + mi * 16 + g;
#pragma unroll
        for (int ni = 0; ni < 4; ++ni) {
            int col = wn * 32 + ni * 8 + 2 * t;
            float b0v = bias[col], b1v = bias[col + 1];
            float r0 = acc[mi][ni][0] + b0v, r1 = acc[mi][ni][1] + b1v;
            float r2 = acc[mi][ni][2] + b0v, r3 = acc[mi][ni][3] + b1v;
            if (do_gelu) { r0 = gelu_t(r0); r1 = gelu_t(r1); r2 = gelu_t(r2); r3 = gelu_t(r3); }
            *(float2*)(d_ACT + (size_t)(b * NN + row) * AW + HOFF + col) = make_float2(r0, r1);
            *(float2*)(d_ACT + (size_t)(b * NN + row + 8) * AW + HOFF + col) = make_float2(r2, r3);
        }
    }
}

// out = fc2 @ gelu(fc1 @ h + b1) + b2 — TF32 mma, 128 nodes x 128 outs x K=64
__global__ __launch_bounds__(256, 2) void k_fc12(const float* __restrict__ W1,
                                                 const float* __restrict__ b1,
                                                 const float* __restrict__ W2,
                                                 const float* __restrict__ b2,
                                                 float* __restrict__ out) {
    const int b = blockIdx.y, nt = blockIdx.x;
    const int tid = threadIdx.x;
    const int wid = tid >> 5, lane = tid & 31;
    const int g = lane >> 2, t = lane & 3;
    const int wm = wid >> 1, wn = wid & 1;       // 4(m) x 2(n)
    __shared__ unsigned sA[128][36];
    __shared__ unsigned sB[32][132];
    __shared__ float sW2[128], sb1v[128];
    __shared__ float sout[128][2];
    float acc[2][8][4] = {};
    if (tid < 128) { sW2[tid] = W2[tid]; sb1v[tid] = b1[tid]; }
    const size_t rowbase = (size_t)(b * NN + nt * 128);

    for (int kc = 0; kc < 2; ++kc) {
        __syncthreads();
#pragma unroll
        for (int i = 0; i < 4; ++i) {
            int f4 = tid + i * 256;
            int row = f4 >> 3, seg = (f4 & 7) * 4;
            float4 v = *(const float4*)(d_ACT + (rowbase + row) * AW + HOFF + kc * 32 + seg);
            *(uint4*)&sA[row][seg] = make_uint4(f2t(v.x), f2t(v.y), f2t(v.z), f2t(v.w));
        }
#pragma unroll
        for (int i = 0; i < 4; ++i) {
            int f4 = tid + i * 256;
            int oo = f4 >> 3, c4l = f4 & 7;
            float4 v = *(const float4*)(W1 + oo * 64 + kc * 32 + c4l * 4);
            sB[c4l * 4 + 0][oo] = f2t(v.x);
            sB[c4l * 4 + 1][oo] = f2t(v.y);
            sB[c4l * 4 + 2][oo] = f2t(v.z);
            sB[c4l * 4 + 3][oo] = f2t(v.w);
        }
        __syncthreads();
#pragma unroll
        for (int kk = 0; kk < 4; ++kk) {
            int k0 = kk * 8;
            unsigned af[2][4];
#pragma unroll
            for (int mi = 0; mi < 2; ++mi) {
                int m = wm * 32 + mi * 16;
                af[mi][0] = sA[m + g][k0 + t];
                af[mi][1] = sA[m + g + 8][k0 + t];
                af[mi][2] = sA[m + g][k0 + t + 4];
                af[mi][3] = sA[m + g + 8][k0 + t + 4];
            }
#pragma unroll
            for (int ni = 0; ni < 8; ++ni) {
                int n = wn * 64 + ni * 8;
                unsigned bf[2];
                bf[0] = sB[k0 + t][n + g];
                bf[1] = sB[k0 + t + 4][n + g];
                MMA8(acc[0][ni], af[0], bf);
                MMA8(acc[1][ni], af[1], bf);
            }
        }
    }
    float b2v = b2[0];
#pragma unroll
    for (int mi = 0; mi < 2; ++mi) {
        float r0sum = 0.f, r1sum = 0.f;
#pragma unroll
        for (int ni = 0; ni < 8; ++ni) {
            int col = wn * 64 + ni * 8 + 2 * t;
            float bb0 = sb1v[col], bb1 = sb1v[col + 1];
            float w20 = sW2[col], w21 = sW2[col + 1];
            r0sum += gelu_t(acc[mi][ni][0] + bb0) * w20 + gelu_t(acc[mi][ni][1] + bb1) * w21;
            r1sum += gelu_t(acc[mi][ni][2] + bb0) * w20 + gelu_t(acc[mi][ni][3] + bb1) * w21;
        }
        r0sum += __shfl_xor_sync(0xffffffffu, r0sum, 1);
        r0sum += __shfl_xor_sync(0xffffffffu, r0sum, 2);
        r1sum += __shfl_xor_sync(0xffffffffu, r1sum, 1);
        r1sum += __shfl_xor_sync(0xffffffffu, r1sum, 2);
        if (t == 0) {
            sout[wm * 32 + mi * 16 + g][wn] = r0sum;
            sout[wm * 32 + mi * 16 + g + 8][wn] = r1sum;
        }
    }
    __syncthreads();
    if (tid < 128)
        out[(size_t)b * NN + nt * 128 + tid] = sout[tid][0] + sout[tid][1] + b2v;
}

// ---------------- launch ----------------
extern "C" void kernel_launch(void* const* d_in, const int* in_sizes, int n_in,
                              void* d_out, int out_size) {
    (void)in_sizes; (void)n_in; (void)out_size;
    const float* x     = (const float*)d_in[0];
    const float* nodes = (const float*)d_in[2];
    const float* nw    = (const float*)d_in[3];
    const int*   edges = (const int*)d_in[4];
    const float* egw   = (const float*)d_in[5];
    const float* modes = (const float*)d_in[6];
    const float* lat   = (const float*)d_in[7];
    const float* fc0W  = (const float*)d_in[8];
    const float* fc0b  = (const float*)d_in[9];
    const float* wc    = (const float*)d_in[10];
    const float* ws    = (const float*)d_in[11];
    const float* w0    = (const float*)d_in[12];
    const float* wsW   = (const float*)d_in[13];
    const float* wsb   = (const float*)d_in[14];
    const float* gwsW  = (const float*)d_in[15];
    const float* gwsb  = (const float*)d_in[16];
    const float* fc1W  = (const float*)d_in[17];
    const float* fc1b  = (const float*)d_in[18];
    const float* fc2W  = (const float*)d_in[19];
    const float* fc2b  = (const float*)d_in[20];
    float* out = (float*)d_out;

    k_setup<<<794, 256>>>(nodes, x, modes, lat, fc0W, fc0b, wc, ws);
    k_hist<<<640, 256>>>(edges);
    k_scan<<<BB, 1024>>>();
    k_scatter<<<640, 256>>>(edges, egw);

    for (int l = 0; l < LL; ++l) {
        k_spectral<<<dim3(NCH, BB), 256>>>(nw);
        k_grad<<<BB * NN / 8, 256>>>();
        k_combine<<<dim3(131, BB), 256>>>(l, w0, gwsW, wsW, wsb, gwsb);
        k_gemm<<<dim3(125, 1, BB), 256>>>(l < LL - 1 ? 1 : 0);
    }
    k_fc12<<<dim3(125, BB), 256>>>(fc1W, fc1b, fc2W, fc2b, out);
}